// round 2
// baseline (speedup 1.0000x reference)
#include <cuda_runtime.h>
#include <math.h>
#include <stdint.h>

// Problem constants
#define BQ 2
#define LQ 4096
#define HQ 1024
#define IQ 2048
#define NQ 16
#define CK 4
#define RQ 64
#define PQ 96   // R + 2N

// -------- device scratch (allocation-free rule: __device__ globals) --------
__device__ float g_proj[(size_t)BQ * LQ * 2 * IQ];  // [B,L,2I] in_proj output (x | gate)
__device__ float g_xl  [(size_t)BQ * LQ * IQ];      // [B,L,I]  conv+silu output
__device__ float g_ssm [(size_t)BQ * LQ * PQ];      // [B,L,96] x_proj output (dt_low|B|C)
__device__ float g_dt  [(size_t)BQ * LQ * IQ];      // [B,L,I]  softplus(dt)
__device__ float g_y   [(size_t)BQ * LQ * IQ];      // [B,L,I]  scan out, then gated in-place

__device__ __forceinline__ float softplusf(float x) {
    return (x > 20.0f) ? x : log1pf(expf(x));
}
__device__ __forceinline__ float siluf(float x) {
    return x / (1.0f + expf(-x));
}

// ---------------------------------------------------------------------------
// SGEMM: C[M,N] = A[M,K(lda)] * W[N,K]^T    (weights stored [out,in] row-major)
// EPI: 0 = plain store, 1 = +bias then softplus
// BM=BN=128, BK=8, 256 threads, 8x8 per thread.
// Requires: M % 128 == 0, K % 8 == 0, K % 4 == 0 for float4 loads. N arbitrary.
// ---------------------------------------------------------------------------
template <int EPI>
__global__ __launch_bounds__(256)
void sgemm_kernel(const float* __restrict__ A, const float* __restrict__ W,
                  float* __restrict__ C, const float* __restrict__ bias,
                  int M, int N, int Kd, int lda)
{
    constexpr int BM = 128, BN = 128, BK = 8;
    __shared__ float As[BK][BM + 4];
    __shared__ float Bs[BK][BN + 4];

    const int tid = threadIdx.x;
    const int m0 = blockIdx.y * BM;
    const int n0 = blockIdx.x * BN;
    const int ty = tid >> 4;        // 0..15
    const int tx = tid & 15;        // 0..15

    // tile loaders: 256 threads, each loads one float4 of A-tile and W-tile
    const int lr = tid >> 1;          // row within tile 0..127
    const int lc = (tid & 1) * 4;     // col 0 or 4
    const float* Aptr = A + (size_t)(m0 + lr) * lda + lc;
    const bool wvalid = (n0 + lr) < N;
    const float* Wptr = W + (size_t)(n0 + lr) * Kd + lc;

    float acc[8][8];
#pragma unroll
    for (int i = 0; i < 8; i++)
#pragma unroll
        for (int j = 0; j < 8; j++) acc[i][j] = 0.0f;

    for (int k0 = 0; k0 < Kd; k0 += BK) {
        float4 av = *(const float4*)(Aptr + k0);
        float4 wv = wvalid ? *(const float4*)(Wptr + k0) : make_float4(0.f, 0.f, 0.f, 0.f);

        __syncthreads();
        As[lc + 0][lr] = av.x;
        As[lc + 1][lr] = av.y;
        As[lc + 2][lr] = av.z;
        As[lc + 3][lr] = av.w;
        Bs[lc + 0][lr] = wv.x;
        Bs[lc + 1][lr] = wv.y;
        Bs[lc + 2][lr] = wv.z;
        Bs[lc + 3][lr] = wv.w;
        __syncthreads();

#pragma unroll
        for (int kk = 0; kk < BK; kk++) {
            float a[8], b[8];
            *(float4*)(a)     = *(const float4*)(&As[kk][ty * 8]);
            *(float4*)(a + 4) = *(const float4*)(&As[kk][ty * 8 + 4]);
            *(float4*)(b)     = *(const float4*)(&Bs[kk][tx * 8]);
            *(float4*)(b + 4) = *(const float4*)(&Bs[kk][tx * 8 + 4]);
#pragma unroll
            for (int i = 0; i < 8; i++)
#pragma unroll
                for (int j = 0; j < 8; j++)
                    acc[i][j] = fmaf(a[i], b[j], acc[i][j]);
        }
    }

#pragma unroll
    for (int i = 0; i < 8; i++) {
        int m = m0 + ty * 8 + i;
#pragma unroll
        for (int j = 0; j < 8; j++) {
            int n = n0 + tx * 8 + j;
            if (n < N) {
                float v = acc[i][j];
                if (EPI == 1) v = softplusf(v + bias[n]);
                C[(size_t)m * N + n] = v;
            }
        }
    }
}

// ---------------------------------------------------------------------------
// depthwise causal conv (K=4) + bias + SiLU.  x = g_proj[:, :, 0:I]
// ---------------------------------------------------------------------------
__global__ void conv_silu_kernel(const float* __restrict__ proj,
                                 const float* __restrict__ cw,
                                 const float* __restrict__ cb,
                                 float* __restrict__ xl)
{
    int idx = blockIdx.x * blockDim.x + threadIdx.x;
    if (idx >= BQ * LQ * IQ) return;
    int i  = idx % IQ;
    int bl = idx / IQ;
    int l  = bl % LQ;

    float w0 = cw[i * CK + 0], w1 = cw[i * CK + 1],
          w2 = cw[i * CK + 2], w3 = cw[i * CK + 3];
    const float* xp = proj + (size_t)bl * (2 * IQ) + i;
    const int str = 2 * IQ;

    float acc = cb[i];
    if (l >= 3) acc = fmaf(xp[-3 * str], w0, acc);
    if (l >= 2) acc = fmaf(xp[-2 * str], w1, acc);
    if (l >= 1) acc = fmaf(xp[-1 * str], w2, acc);
    acc = fmaf(xp[0], w3, acc);

    xl[idx] = siluf(acc);
}

// ---------------------------------------------------------------------------
// selective scan: each warp owns 2 channels; lane = (sub<<4) | n.
// h[n] <- h[n]*exp(dt*A[n]) + dt*B[n]*x ;  y = sum_n h[n]*C[n]
// ---------------------------------------------------------------------------
__global__ __launch_bounds__(256)
void scan_kernel(const float* __restrict__ xl,
                 const float* __restrict__ dt,
                 const float* __restrict__ ssm,
                 const float* __restrict__ A_log,
                 float* __restrict__ y)
{
    int gtid = blockIdx.x * blockDim.x + threadIdx.x;
    int warp = gtid >> 5;
    int lane = threadIdx.x & 31;
    int sub  = lane >> 4;     // which of 2 channels in this warp
    int n    = lane & 15;     // state index
    int ch   = warp * 2 + sub;
    if (ch >= BQ * IQ) return;
    int b = ch / IQ;
    int i = ch % IQ;

    const float Av = -expf(A_log[i * NQ + n]);

    const float* xp  = xl  + (size_t)b * LQ * IQ + i;
    const float* dtp = dt  + (size_t)b * LQ * IQ + i;
    const float* Bp  = ssm + (size_t)b * LQ * PQ + RQ + n;
    const float* Cp  = Bp + NQ;
    float*       yp  = y   + (size_t)b * LQ * IQ + i;

    float h = 0.0f;
    for (int l = 0; l < LQ; l++) {
        float xv  = xp [(size_t)l * IQ];
        float dtv = dtp[(size_t)l * IQ];
        float Bn  = Bp [(size_t)l * PQ];
        float Cn  = Cp [(size_t)l * PQ];

        float dA = expf(dtv * Av);
        h = fmaf(h, dA, dtv * Bn * xv);
        float c = h * Cn;
        // reduce over n (xor within 16-lane halves)
        c += __shfl_xor_sync(0xffffffffu, c, 8);
        c += __shfl_xor_sync(0xffffffffu, c, 4);
        c += __shfl_xor_sync(0xffffffffu, c, 2);
        c += __shfl_xor_sync(0xffffffffu, c, 1);
        if (n == 0) yp[(size_t)l * IQ] = c;
    }
}

// ---------------------------------------------------------------------------
// y = (y_scan + xl*D) * silu(gate)   (in-place on g_y)
// ---------------------------------------------------------------------------
__global__ void gate_kernel(const float* __restrict__ proj,
                            const float* __restrict__ xl,
                            const float* __restrict__ Dw,
                            float* __restrict__ y)
{
    int idx = blockIdx.x * blockDim.x + threadIdx.x;
    if (idx >= BQ * LQ * IQ) return;
    int i  = idx % IQ;
    int bl = idx / IQ;
    float g = proj[(size_t)bl * (2 * IQ) + IQ + i];
    y[idx] = (y[idx] + xl[idx] * Dw[i]) * siluf(g);
}

// ---------------------------------------------------------------------------
extern "C" void kernel_launch(void* const* d_in, const int* in_sizes, int n_in,
                              void* d_out, int out_size)
{
    const float* hidden    = (const float*)d_in[0];  // [B,L,H]
    const float* in_proj_w = (const float*)d_in[1];  // [2I,H]
    const float* conv_w    = (const float*)d_in[2];  // [I,K]
    const float* conv_b    = (const float*)d_in[3];  // [I]
    const float* x_proj_w  = (const float*)d_in[4];  // [96,I]
    const float* dt_proj_w = (const float*)d_in[5];  // [I,R]
    const float* dt_proj_b = (const float*)d_in[6];  // [I]
    const float* A_log     = (const float*)d_in[7];  // [I,N]
    const float* Dw        = (const float*)d_in[8];  // [I]
    const float* out_proj_w= (const float*)d_in[9];  // [H,I]
    float* out = (float*)d_out;                      // [B,L,H]

    float *proj, *xl, *ssm, *dt, *y;
    cudaGetSymbolAddress((void**)&proj, g_proj);
    cudaGetSymbolAddress((void**)&xl,   g_xl);
    cudaGetSymbolAddress((void**)&ssm,  g_ssm);
    cudaGetSymbolAddress((void**)&dt,   g_dt);
    cudaGetSymbolAddress((void**)&y,    g_y);

    const int M = BQ * LQ;  // 8192

    // 1) in_proj: proj[M, 2I] = hidden[M,H] @ in_proj_w[2I,H]^T
    {
        dim3 grid((2 * IQ) / 128, M / 128);
        sgemm_kernel<0><<<grid, 256>>>(hidden, in_proj_w, proj, nullptr,
                                       M, 2 * IQ, HQ, HQ);
    }
    // 2) depthwise conv + silu -> xl[M, I]
    {
        int total = BQ * LQ * IQ;
        conv_silu_kernel<<<(total + 255) / 256, 256>>>(proj, conv_w, conv_b, xl);
    }
    // 3) x_proj: ssm[M, 96] = xl[M,I] @ x_proj_w[96,I]^T
    {
        dim3 grid(1, M / 128);
        sgemm_kernel<0><<<grid, 256>>>(xl, x_proj_w, ssm, nullptr,
                                       M, PQ, IQ, IQ);
    }
    // 4) dt_proj + bias + softplus: dt[M, I] = softplus(ssm[:, :64] @ dt_proj_w[I,64]^T + b)
    {
        dim3 grid(IQ / 128, M / 128);
        sgemm_kernel<1><<<grid, 256>>>(ssm, dt_proj_w, dt, dt_proj_b,
                                       M, IQ, RQ, PQ);
    }
    // 5) selective scan -> y[M, I]
    {
        int nthreads = (BQ * IQ / 2) * 32;   // 2 channels per warp
        scan_kernel<<<nthreads / 256, 256>>>(xl, dt, ssm, A_log, y);
    }
    // 6) gating: y = (y + xl*D) * silu(gate)
    {
        int total = BQ * LQ * IQ;
        gate_kernel<<<(total + 255) / 256, 256>>>(proj, xl, Dw, y);
    }
    // 7) out_proj: out[M, H] = y[M,I] @ out_proj_w[H,I]^T
    {
        dim3 grid(HQ / 128, M / 128);
        sgemm_kernel<0><<<grid, 256>>>(y, out_proj_w, out, nullptr,
                                       M, HQ, IQ, IQ);
    }
}

// round 13
// speedup vs baseline: 1.0397x; 1.0397x over previous
#include <cuda_runtime.h>
#include <cuda_bf16.h>
#include <math.h>
#include <stdint.h>

// Problem constants
#define BQ 2
#define LQ 4096
#define HQ 1024
#define IQ 2048
#define NQ 16
#define CK 4
#define RQ 64
#define PQ 96   // R + 2N

// ===========================================================================
// device scratch (allocation-free rule: __device__ globals)
// ===========================================================================
__device__ __align__(16) float g_proj[(size_t)BQ * LQ * 2 * IQ];  // 134MB (x | gate)
__device__ __align__(16) float g_xl  [(size_t)BQ * LQ * IQ];      // 67MB conv+silu out
__device__ __align__(16) float g_ssm [(size_t)BQ * LQ * PQ];      // 3MB  x_proj out
__device__ __align__(16) float g_dt  [(size_t)BQ * LQ * IQ];      // 67MB softplus(dt)
__device__ __align__(16) float g_y   [(size_t)BQ * LQ * IQ];      // 67MB scan out

// bf16 arena (120MB) with phase-overlaid layout:
//   [0,               12582912)  wout3  [1024 x 6144]  (persistent)
//   [25165824,        75497472)  hs3    [8192 x 3072]  (phase 1-2 only)
//   [75497472,       100663296)  win3   [4096 x 3072]  (phase 1-2 only)
//   [25165824,       125829120)  y3     [8192 x 6144]  (phase 7-8, reuses hs3/win3)
#define SCRATCH_BYTES 125829120ull
#define OFF_WOUT3 0ull
#define OFF_HS3   25165824ull
#define OFF_WIN3  75497472ull
#define OFF_Y3    25165824ull
__device__ __align__(256) char g_arena[SCRATCH_BYTES];

__device__ __forceinline__ float softplusf(float x) {
    return (x > 20.0f) ? x : log1pf(expf(x));
}
__device__ __forceinline__ float siluf(float x) {
    return x / (1.0f + expf(-x));
}

// ===========================================================================
// splits  (triple-split single-GEMM trick:
//   A' = [Ah | Ah | Al], W' = [Wh | Wl | Wh];  A'@W'^T ~= fp32 A@W^T)
// ===========================================================================
// activations: out[r,c]=hi, out[r,K+c]=hi, out[r,2K+c]=lo
__global__ void split3_A_kernel(const float* __restrict__ in,
                                __nv_bfloat16* __restrict__ out,
                                int rows, int K)
{
    int idx = blockIdx.x * blockDim.x + threadIdx.x;
    if (idx >= rows * K) return;
    int r = idx / K, c = idx % K;
    float x = in[idx];
    __nv_bfloat16 h = __float2bfloat16(x);
    __nv_bfloat16 l = __float2bfloat16(x - __bfloat162float(h));
    size_t base = (size_t)r * 3 * K;
    out[base + c] = h;
    out[base + K + c] = h;
    out[base + 2 * K + c] = l;
}
// weights: out[r,c]=hi, out[r,K+c]=lo, out[r,2K+c]=hi
__global__ void split3_W_kernel(const float* __restrict__ in,
                                __nv_bfloat16* __restrict__ out,
                                int rows, int K)
{
    int idx = blockIdx.x * blockDim.x + threadIdx.x;
    if (idx >= rows * K) return;
    int r = idx / K, c = idx % K;
    float x = in[idx];
    __nv_bfloat16 h = __float2bfloat16(x);
    __nv_bfloat16 l = __float2bfloat16(x - __bfloat162float(h));
    size_t base = (size_t)r * 3 * K;
    out[base + c] = h;
    out[base + K + c] = l;
    out[base + 2 * K + c] = h;
}

// ===========================================================================
// bf16 mma.sync GEMM:  C[M,N] = A[M,Kp] @ W[N,Kp]^T,  fp32 accum/out.
// BM=BN=128, BK=64, 256 threads (8 warps, each 64x32 output).
// Register-double-buffered global loads (no cp.async).
// Fragments assembled with plain 32-bit shared loads in the canonical
// mma.m16n8k16.row.col thread mapping (no ldmatrix).
// smem rows padded to 144B -> conflict-free fragment loads.
// ===========================================================================
#define GBM 128
#define GBN 128
#define GBK 64
#define GROW_BYTES 144
#define GTILE_BYTES (128 * GROW_BYTES)          // 18432
#define GSMEM_BYTES (2 * GTILE_BYTES)           // A + W = 36864

__device__ __forceinline__ void mma16816(float* c, const uint32_t* a, const uint32_t* b) {
    asm volatile(
        "mma.sync.aligned.m16n8k16.row.col.f32.bf16.bf16.f32 "
        "{%0,%1,%2,%3}, {%4,%5,%6,%7}, {%8,%9}, {%0,%1,%2,%3};"
        : "+f"(c[0]), "+f"(c[1]), "+f"(c[2]), "+f"(c[3])
        : "r"(a[0]), "r"(a[1]), "r"(a[2]), "r"(a[3]), "r"(b[0]), "r"(b[1]));
}

__global__ __launch_bounds__(256)
void tc_gemm_kernel(const __nv_bfloat16* __restrict__ A,   // [M, Kp]
                    const __nv_bfloat16* __restrict__ W,   // [N, Kp]
                    float* __restrict__ C,
                    int M, int N, int Kp)
{
    extern __shared__ char smem[];
    char* As = smem;                 // [128 rows][144B], 128B data per row
    char* Ws = smem + GTILE_BYTES;   // [128 rows][144B]

    const int tid  = threadIdx.x;
    const int wid  = tid >> 5;
    const int lane = tid & 31;
    const int wm   = wid & 1;      // warp row (0..1): 64 M-rows each
    const int wn   = wid >> 1;     // warp col (0..3): 32 N-cols each
    const int grp  = lane >> 2;    // 0..7
    const int tig  = lane & 3;     // 0..3

    const int m0 = blockIdx.y * GBM;
    const int n0 = blockIdx.x * GBN;

    const __nv_bfloat16* Abase = A + (size_t)m0 * Kp;
    const __nv_bfloat16* Wbase = W + (size_t)n0 * Kp;

    // global/smem tile loader pattern: thread -> (row tid>>3, 16B chunk tid&7)
    const int lrow  = tid >> 3;          // 0..31 (+ j*32)
    const int lcolB = (tid & 7) * 16;    // byte col 0..112

    float acc[4][4][4];
#pragma unroll
    for (int i = 0; i < 4; i++)
#pragma unroll
        for (int j = 0; j < 4; j++)
#pragma unroll
            for (int k = 0; k < 4; k++) acc[i][j][k] = 0.0f;

    const int NKB = Kp / GBK;

    // preload k-block 0 into registers
    uint4 rA[4], rW[4];
#pragma unroll
    for (int j = 0; j < 4; j++) {
        int r = lrow + j * 32;
        rA[j] = *(const uint4*)((const char*)(Abase + (size_t)r * Kp) + lcolB);
        rW[j] = *(const uint4*)((const char*)(Wbase + (size_t)r * Kp) + lcolB);
    }

    for (int kb = 0; kb < NKB; kb++) {
        // store current k-block registers into smem
#pragma unroll
        for (int j = 0; j < 4; j++) {
            int r = lrow + j * 32;
            *(uint4*)(As + r * GROW_BYTES + lcolB) = rA[j];
            *(uint4*)(Ws + r * GROW_BYTES + lcolB) = rW[j];
        }
        __syncthreads();

        // prefetch next k-block into registers (hides global latency under MMA)
        if (kb + 1 < NKB) {
            const __nv_bfloat16* an = Abase + (size_t)(kb + 1) * GBK;
            const __nv_bfloat16* wp = Wbase + (size_t)(kb + 1) * GBK;
#pragma unroll
            for (int j = 0; j < 4; j++) {
                int r = lrow + j * 32;
                rA[j] = *(const uint4*)((const char*)(an + (size_t)r * Kp) + lcolB);
                rW[j] = *(const uint4*)((const char*)(wp + (size_t)r * Kp) + lcolB);
            }
        }

        // compute: 4 k-slices of 16
#pragma unroll
        for (int ks = 0; ks < 4; ks++) {
            const int kbyte = ks * 32;   // 16 bf16 = 32B

            // A fragments, canonical m16k16 row-major mapping:
            //  a0: (row=grp,    k=tig*2..+1)   a1: (row=grp+8,  same k)
            //  a2: (row=grp,    k=tig*2+8..+9) a3: (row=grp+8,  k+8)
            uint32_t af[4][4];
#pragma unroll
            for (int mt = 0; mt < 4; mt++) {
                const char* p = As + (wm * 64 + mt * 16 + grp) * GROW_BYTES
                                   + kbyte + tig * 4;
                af[mt][0] = *(const uint32_t*)(p);
                af[mt][1] = *(const uint32_t*)(p + 8 * GROW_BYTES);
                af[mt][2] = *(const uint32_t*)(p + 16);
                af[mt][3] = *(const uint32_t*)(p + 8 * GROW_BYTES + 16);
            }
            // B fragments, canonical n8k16 col-major mapping:
            //  b0: (n=grp, k=tig*2..+1)  b1: (n=grp, k=tig*2+8..+9)
            uint32_t bf[4][2];
#pragma unroll
            for (int nt = 0; nt < 4; nt++) {
                const char* p = Ws + (wn * 32 + nt * 8 + grp) * GROW_BYTES
                                   + kbyte + tig * 4;
                bf[nt][0] = *(const uint32_t*)(p);
                bf[nt][1] = *(const uint32_t*)(p + 16);
            }
#pragma unroll
            for (int mt = 0; mt < 4; mt++)
#pragma unroll
                for (int nt = 0; nt < 4; nt++)
                    mma16816(acc[mt][nt], af[mt], bf[nt]);
        }
        __syncthreads();
    }

    // epilogue (canonical C mapping: c0,c1 at (row=grp, col=tig*2), c2,c3 at row+8)
#pragma unroll
    for (int mt = 0; mt < 4; mt++) {
        int r0 = m0 + wm * 64 + mt * 16 + grp;
#pragma unroll
        for (int nt = 0; nt < 4; nt++) {
            int cc = n0 + wn * 32 + nt * 8 + tig * 2;
            *(float2*)(C + (size_t)r0 * N + cc) =
                make_float2(acc[mt][nt][0], acc[mt][nt][1]);
            *(float2*)(C + (size_t)(r0 + 8) * N + cc) =
                make_float2(acc[mt][nt][2], acc[mt][nt][3]);
        }
    }
}

// ===========================================================================
// fp32 SGEMM (small GEMMs): C[M,N] = A[M,K(lda)] * W[N,K]^T
// EPI: 0 = plain, 1 = +bias then softplus
// ===========================================================================
template <int EPI>
__global__ __launch_bounds__(256)
void sgemm_kernel(const float* __restrict__ A, const float* __restrict__ W,
                  float* __restrict__ C, const float* __restrict__ bias,
                  int M, int N, int Kd, int lda)
{
    constexpr int BM = 128, BN = 128, BK = 8;
    __shared__ float As[BK][BM + 4];
    __shared__ float Bs[BK][BN + 4];

    const int tid = threadIdx.x;
    const int m0 = blockIdx.y * BM;
    const int n0 = blockIdx.x * BN;
    const int ty = tid >> 4;
    const int tx = tid & 15;

    const int lr = tid >> 1;
    const int lc = (tid & 1) * 4;
    const float* Aptr = A + (size_t)(m0 + lr) * lda + lc;
    const bool wvalid = (n0 + lr) < N;
    const float* Wptr = W + (size_t)(n0 + lr) * Kd + lc;

    float acc[8][8];
#pragma unroll
    for (int i = 0; i < 8; i++)
#pragma unroll
        for (int j = 0; j < 8; j++) acc[i][j] = 0.0f;

    for (int k0 = 0; k0 < Kd; k0 += BK) {
        float4 av = *(const float4*)(Aptr + k0);
        float4 wv = wvalid ? *(const float4*)(Wptr + k0) : make_float4(0.f, 0.f, 0.f, 0.f);

        __syncthreads();
        As[lc + 0][lr] = av.x;
        As[lc + 1][lr] = av.y;
        As[lc + 2][lr] = av.z;
        As[lc + 3][lr] = av.w;
        Bs[lc + 0][lr] = wv.x;
        Bs[lc + 1][lr] = wv.y;
        Bs[lc + 2][lr] = wv.z;
        Bs[lc + 3][lr] = wv.w;
        __syncthreads();

#pragma unroll
        for (int kk = 0; kk < BK; kk++) {
            float a[8], b[8];
            *(float4*)(a)     = *(const float4*)(&As[kk][ty * 8]);
            *(float4*)(a + 4) = *(const float4*)(&As[kk][ty * 8 + 4]);
            *(float4*)(b)     = *(const float4*)(&Bs[kk][tx * 8]);
            *(float4*)(b + 4) = *(const float4*)(&Bs[kk][tx * 8 + 4]);
#pragma unroll
            for (int i = 0; i < 8; i++)
#pragma unroll
                for (int j = 0; j < 8; j++)
                    acc[i][j] = fmaf(a[i], b[j], acc[i][j]);
        }
    }

#pragma unroll
    for (int i = 0; i < 8; i++) {
        int m = m0 + ty * 8 + i;
#pragma unroll
        for (int j = 0; j < 8; j++) {
            int n = n0 + tx * 8 + j;
            if (n < N) {
                float v = acc[i][j];
                if (EPI == 1) v = softplusf(v + bias[n]);
                C[(size_t)m * N + n] = v;
            }
        }
    }
}

// ===========================================================================
// depthwise causal conv (K=4) + bias + SiLU
// ===========================================================================
__global__ void conv_silu_kernel(const float* __restrict__ proj,
                                 const float* __restrict__ cw,
                                 const float* __restrict__ cb,
                                 float* __restrict__ xl)
{
    int idx = blockIdx.x * blockDim.x + threadIdx.x;
    if (idx >= BQ * LQ * IQ) return;
    int i  = idx % IQ;
    int bl = idx / IQ;
    int l  = bl % LQ;

    float w0 = cw[i * CK + 0], w1 = cw[i * CK + 1],
          w2 = cw[i * CK + 2], w3 = cw[i * CK + 3];
    const float* xp = proj + (size_t)bl * (2 * IQ) + i;
    const int str = 2 * IQ;

    float acc = cb[i];
    if (l >= 3) acc = fmaf(xp[-3 * str], w0, acc);
    if (l >= 2) acc = fmaf(xp[-2 * str], w1, acc);
    if (l >= 1) acc = fmaf(xp[-1 * str], w2, acc);
    acc = fmaf(xp[0], w3, acc);

    xl[idx] = siluf(acc);
}

// ===========================================================================
// selective scan: each warp owns 2 channels; lane = (sub<<4) | n
// ===========================================================================
__global__ __launch_bounds__(256)
void scan_kernel(const float* __restrict__ xl,
                 const float* __restrict__ dt,
                 const float* __restrict__ ssm,
                 const float* __restrict__ A_log,
                 float* __restrict__ y)
{
    int gtid = blockIdx.x * blockDim.x + threadIdx.x;
    int warp = gtid >> 5;
    int lane = threadIdx.x & 31;
    int sub  = lane >> 4;
    int n    = lane & 15;
    int ch   = warp * 2 + sub;
    if (ch >= BQ * IQ) return;
    int b = ch / IQ;
    int i = ch % IQ;

    const float Av = -expf(A_log[i * NQ + n]);

    const float* xp  = xl  + (size_t)b * LQ * IQ + i;
    const float* dtp = dt  + (size_t)b * LQ * IQ + i;
    const float* Bp  = ssm + (size_t)b * LQ * PQ + RQ + n;
    const float* Cp  = Bp + NQ;
    float*       yp  = y   + (size_t)b * LQ * IQ + i;

    float h = 0.0f;
    for (int l = 0; l < LQ; l++) {
        float xv  = xp [(size_t)l * IQ];
        float dtv = dtp[(size_t)l * IQ];
        float Bn  = Bp [(size_t)l * PQ];
        float Cn  = Cp [(size_t)l * PQ];

        float dA = expf(dtv * Av);
        h = fmaf(h, dA, dtv * Bn * xv);
        float c = h * Cn;
        c += __shfl_xor_sync(0xffffffffu, c, 8);
        c += __shfl_xor_sync(0xffffffffu, c, 4);
        c += __shfl_xor_sync(0xffffffffu, c, 2);
        c += __shfl_xor_sync(0xffffffffu, c, 1);
        if (n == 0) yp[(size_t)l * IQ] = c;
    }
}

// ===========================================================================
// gating fused with triple bf16 split:
//   v = (y_scan + xl*D) * silu(gate);  y3 = [vh | vh | vl]
// ===========================================================================
__global__ void gate_split3_kernel(const float* __restrict__ proj,
                                   const float* __restrict__ xl,
                                   const float* __restrict__ Dw,
                                   const float* __restrict__ yscan,
                                   __nv_bfloat16* __restrict__ y3)
{
    int idx = blockIdx.x * blockDim.x + threadIdx.x;
    if (idx >= BQ * LQ * IQ) return;
    int i  = idx % IQ;
    int bl = idx / IQ;
    float g = proj[(size_t)bl * (2 * IQ) + IQ + i];
    float v = (yscan[idx] + xl[idx] * Dw[i]) * siluf(g);
    __nv_bfloat16 h = __float2bfloat16(v);
    __nv_bfloat16 l = __float2bfloat16(v - __bfloat162float(h));
    size_t base = (size_t)bl * 3 * IQ;
    y3[base + i] = h;
    y3[base + IQ + i] = h;
    y3[base + 2 * IQ + i] = l;
}

// ===========================================================================
extern "C" void kernel_launch(void* const* d_in, const int* in_sizes, int n_in,
                              void* d_out, int out_size)
{
    const float* hidden    = (const float*)d_in[0];  // [B,L,H]
    const float* in_proj_w = (const float*)d_in[1];  // [2I,H]
    const float* conv_w    = (const float*)d_in[2];  // [I,K]
    const float* conv_b    = (const float*)d_in[3];  // [I]
    const float* x_proj_w  = (const float*)d_in[4];  // [96,I]
    const float* dt_proj_w = (const float*)d_in[5];  // [I,R]
    const float* dt_proj_b = (const float*)d_in[6];  // [I]
    const float* A_log     = (const float*)d_in[7];  // [I,N]
    const float* Dw        = (const float*)d_in[8];  // [I]
    const float* out_proj_w= (const float*)d_in[9];  // [H,I]  (I = 2048 inner dim!)
    float* out = (float*)d_out;                      // [B,L,H]

    float *proj, *xl, *ssm, *dt, *y;
    char* arena;
    cudaGetSymbolAddress((void**)&proj,  g_proj);
    cudaGetSymbolAddress((void**)&xl,    g_xl);
    cudaGetSymbolAddress((void**)&ssm,   g_ssm);
    cudaGetSymbolAddress((void**)&dt,    g_dt);
    cudaGetSymbolAddress((void**)&y,     g_y);
    cudaGetSymbolAddress((void**)&arena, g_arena);

    __nv_bfloat16* wout3 = (__nv_bfloat16*)(arena + OFF_WOUT3);
    __nv_bfloat16* hs3   = (__nv_bfloat16*)(arena + OFF_HS3);
    __nv_bfloat16* win3  = (__nv_bfloat16*)(arena + OFF_WIN3);
    __nv_bfloat16* y3    = (__nv_bfloat16*)(arena + OFF_Y3);   // overlays hs3/win3

    cudaFuncSetAttribute(tc_gemm_kernel,
                         cudaFuncAttributeMaxDynamicSharedMemorySize, GSMEM_BYTES);

    const int M = BQ * LQ;  // 8192

    // 0) bf16 triple splits
    //    FIX: out_proj_w is [H, I] -> K = IQ (was wrongly 2*IQ; read 2x past the
    //    end of the allocation -> the illegal memory access of rounds 6/11/12).
    {
        int n3 = HQ * IQ;   // 1024 x 2048 elements
        split3_W_kernel<<<(n3 + 255) / 256, 256>>>(out_proj_w, wout3, HQ, IQ);
        int n1 = M * HQ;
        split3_A_kernel<<<(n1 + 255) / 256, 256>>>(hidden, hs3, M, HQ);
        int n2 = 2 * IQ * HQ;
        split3_W_kernel<<<(n2 + 255) / 256, 256>>>(in_proj_w, win3, 2 * IQ, HQ);
    }
    // 1) in_proj on tensor cores: proj[M, 2I] = hidden @ in_proj_w^T  (K'=3072)
    {
        dim3 grid((2 * IQ) / GBN, M / GBM);
        tc_gemm_kernel<<<grid, 256, GSMEM_BYTES>>>(hs3, win3, proj, M, 2 * IQ, 3 * HQ);
    }
    // 2) depthwise conv + silu -> xl[M, I]
    {
        int total = BQ * LQ * IQ;
        conv_silu_kernel<<<(total + 255) / 256, 256>>>(proj, conv_w, conv_b, xl);
    }
    // 3) x_proj: ssm[M, 96] = xl @ x_proj_w^T   (fp32)
    {
        dim3 grid(1, M / 128);
        sgemm_kernel<0><<<grid, 256>>>(xl, x_proj_w, ssm, nullptr, M, PQ, IQ, IQ);
    }
    // 4) dt_proj + softplus (fp32)
    {
        dim3 grid(IQ / 128, M / 128);
        sgemm_kernel<1><<<grid, 256>>>(ssm, dt_proj_w, dt, dt_proj_b, M, IQ, RQ, PQ);
    }
    // 5) selective scan -> y[M, I]
    {
        int nthreads = (BQ * IQ / 2) * 32;
        scan_kernel<<<nthreads / 256, 256>>>(xl, dt, ssm, A_log, y);
    }
    // 6) gating + triple split -> y3 [M, 3*I=6144]
    {
        int total = BQ * LQ * IQ;
        gate_split3_kernel<<<(total + 255) / 256, 256>>>(proj, xl, Dw, y, y3);
    }
    // 7) out_proj on tensor cores: out[M, H] = y @ out_proj_w^T  (K'=3*I=6144)
    {
        dim3 grid(HQ / GBN, M / GBM);
        tc_gemm_kernel<<<grid, 256, GSMEM_BYTES>>>(y3, wout3, out, M, HQ, 3 * IQ);
    }
}

// round 17
// speedup vs baseline: 1.5781x; 1.5179x over previous
#include <cuda_runtime.h>
#include <cuda_bf16.h>
#include <math.h>
#include <stdint.h>

// Problem constants
#define BQ 2
#define LQ 4096
#define HQ 1024
#define IQ 2048
#define NQ 16
#define CK 4
#define RQ 64
#define PQ 96   // R + 2N

// ===========================================================================
// device scratch (allocation-free rule: __device__ globals)
// ===========================================================================
__device__ __align__(16) float g_proj[(size_t)BQ * LQ * 2 * IQ];  // (x | gate)
__device__ __align__(16) float g_xl  [(size_t)BQ * LQ * IQ];      // conv+silu out
__device__ __align__(16) float g_ssm [(size_t)BQ * LQ * PQ];      // x_proj out
__device__ __align__(16) float g_dt  [(size_t)BQ * LQ * IQ];      // softplus(dt)
__device__ __align__(16) float g_y   [(size_t)BQ * LQ * IQ];      // scan out

// bf16 arena (120MB) with phase-overlaid layout:
//   [0,        12582912)  wout3 [1024 x 6144] (persistent)
//   [25165824, 75497472)  hs3   [8192 x 3072] (phase 1-2)
//   [75497472,100663296)  win3  [4096 x 3072] (phase 1-2)
//   [25165824,125829120)  y3    [8192 x 6144] (phase 7-8, reuses hs3/win3)
#define SCRATCH_BYTES 125829120ull
#define OFF_WOUT3 0ull
#define OFF_HS3   25165824ull
#define OFF_WIN3  75497472ull
#define OFF_Y3    25165824ull
__device__ __align__(256) char g_arena[SCRATCH_BYTES];

__device__ __forceinline__ float softplusf(float x) {
    return (x > 20.0f) ? x : log1pf(expf(x));
}
__device__ __forceinline__ float siluf(float x) {
    return x / (1.0f + expf(-x));
}

// ===========================================================================
// splits  (triple-split single-GEMM trick:
//   A' = [Ah | Ah | Al], W' = [Wh | Wl | Wh];  A'@W'^T ~= fp32 A@W^T)
// ===========================================================================
__global__ void split3_A_kernel(const float* __restrict__ in,
                                __nv_bfloat16* __restrict__ out,
                                int rows, int K)
{
    int idx = blockIdx.x * blockDim.x + threadIdx.x;
    if (idx >= rows * K) return;
    int r = idx / K, c = idx % K;
    float x = in[idx];
    __nv_bfloat16 h = __float2bfloat16(x);
    __nv_bfloat16 l = __float2bfloat16(x - __bfloat162float(h));
    size_t base = (size_t)r * 3 * K;
    out[base + c] = h;
    out[base + K + c] = h;
    out[base + 2 * K + c] = l;
}
__global__ void split3_W_kernel(const float* __restrict__ in,
                                __nv_bfloat16* __restrict__ out,
                                int rows, int K)
{
    int idx = blockIdx.x * blockDim.x + threadIdx.x;
    if (idx >= rows * K) return;
    int r = idx / K, c = idx % K;
    float x = in[idx];
    __nv_bfloat16 h = __float2bfloat16(x);
    __nv_bfloat16 l = __float2bfloat16(x - __bfloat162float(h));
    size_t base = (size_t)r * 3 * K;
    out[base + c] = h;
    out[base + K + c] = l;
    out[base + 2 * K + c] = h;
}

// ===========================================================================
// bf16 mma.sync GEMM:  C[M,N] = A[M,Kp] @ W[N,Kp]^T,  fp32 accum/out.
// BM=BN=128, BK=64, 256 threads (8 warps, each 64x32 output).
// 2-stage cp.async pipeline + ldmatrix fragment loads (low LSU-op count).
// smem rows padded to 144B -> conflict-free ldmatrix.
// ===========================================================================
#define GBM 128
#define GBN 128
#define GBK 64
#define GROW_BYTES 144
#define GTILE_BYTES (128 * GROW_BYTES)          // 18432
#define GSTAGE_BYTES (2 * GTILE_BYTES)          // A + W = 36864
#define GSMEM_BYTES (2 * GSTAGE_BYTES)          // 2 stages = 73728

__device__ __forceinline__ uint32_t smem_u32(const void* p) {
    uint32_t a;
    asm("{ .reg .u64 t; cvta.to.shared.u64 t, %1; cvt.u32.u64 %0, t; }" : "=r"(a) : "l"(p));
    return a;
}
__device__ __forceinline__ void cp_async16(uint32_t saddr, const void* g) {
    asm volatile("cp.async.cg.shared.global [%0], [%1], 16;" :: "r"(saddr), "l"(g));
}
__device__ __forceinline__ void cp_commit() {
    asm volatile("cp.async.commit_group;");
}
template <int Nn>
__device__ __forceinline__ void cp_wait() {
    asm volatile("cp.async.wait_group %0;" :: "n"(Nn));
}
__device__ __forceinline__ void ldmx4(uint32_t* r, uint32_t saddr) {
    asm volatile("ldmatrix.sync.aligned.m8n8.x4.shared.b16 {%0,%1,%2,%3}, [%4];"
                 : "=r"(r[0]), "=r"(r[1]), "=r"(r[2]), "=r"(r[3]) : "r"(saddr));
}
__device__ __forceinline__ void mma16816(float* c, const uint32_t* a, const uint32_t* b) {
    asm volatile(
        "mma.sync.aligned.m16n8k16.row.col.f32.bf16.bf16.f32 "
        "{%0,%1,%2,%3}, {%4,%5,%6,%7}, {%8,%9}, {%0,%1,%2,%3};"
        : "+f"(c[0]), "+f"(c[1]), "+f"(c[2]), "+f"(c[3])
        : "r"(a[0]), "r"(a[1]), "r"(a[2]), "r"(a[3]), "r"(b[0]), "r"(b[1]));
}

__global__ __launch_bounds__(256, 2)
void tc_gemm_kernel(const __nv_bfloat16* __restrict__ A,   // [M, Kp]
                    const __nv_bfloat16* __restrict__ W,   // [N, Kp]
                    float* __restrict__ C,
                    int M, int N, int Kp)
{
    extern __shared__ char smem[];
    const uint32_t sbase = smem_u32(smem);
    const int tid  = threadIdx.x;
    const int wid  = tid >> 5;
    const int lane = tid & 31;
    const int wm   = wid & 1;      // warp row (0..1): 64 M-rows each
    const int wn   = wid >> 1;     // warp col (0..3): 32 N-cols each
    const int grp  = lane >> 2;    // 0..7
    const int tig  = lane & 3;     // 0..3

    const int m0 = blockIdx.y * GBM;
    const int n0 = blockIdx.x * GBN;

    const __nv_bfloat16* Abase = A + (size_t)m0 * Kp;
    const __nv_bfloat16* Wbase = W + (size_t)n0 * Kp;

    // tile loader pattern: thread -> (row tid>>3, 16B chunk tid&7), 4 rows each
    const int lrow  = tid >> 3;          // 0..31 (+ j*32)
    const int lcolB = (tid & 7) * 16;    // byte col 0..112

    const int NKB = Kp / GBK;

    auto load_stage = [&](int s, int kb) {
        const uint32_t aOff = sbase + s * GSTAGE_BYTES;
        const uint32_t wOff = aOff + GTILE_BYTES;
        const __nv_bfloat16* ak = Abase + (size_t)kb * GBK;
        const __nv_bfloat16* wk = Wbase + (size_t)kb * GBK;
#pragma unroll
        for (int j = 0; j < 4; j++) {
            int r = lrow + j * 32;
            cp_async16(aOff + r * GROW_BYTES + lcolB,
                       (const char*)(ak + (size_t)r * Kp) + lcolB);
        }
#pragma unroll
        for (int j = 0; j < 4; j++) {
            int r = lrow + j * 32;
            cp_async16(wOff + r * GROW_BYTES + lcolB,
                       (const char*)(wk + (size_t)r * Kp) + lcolB);
        }
    };

    float acc[4][4][4];
#pragma unroll
    for (int i = 0; i < 4; i++)
#pragma unroll
        for (int j = 0; j < 4; j++)
#pragma unroll
            for (int k = 0; k < 4; k++) acc[i][j][k] = 0.0f;

    load_stage(0, 0);
    cp_commit();

    // ldmatrix lane addressing (constant per thread)
    //  A x4: lanes 0-15 -> rows 0-15 at +0B; lanes 16-31 -> rows 0-15 at +16B
    //    -> regs = (r0-7/k0-7),(r8-15/k0-7),(r0-7/k8-15),(r8-15/k8-15) = a0..a3
    const int a_row = (lane & 15);
    const int a_kby = (lane >> 4) * 16;
    //  B x4: lanes 0-7 rows0-7 at +0; 8-15 rows0-7 at +16; 16-23 rows8-15 at +0;
    //        24-31 rows8-15 at +16  -> m0=(n0-7,b0) m1=(n0-7,b1) m2/m3 = n8-15
    const int b_row = ((lane >> 4) << 3) + (lane & 7);
    const int b_kby = ((lane >> 3) & 1) * 16;

    for (int kb = 0; kb < NKB; kb++) {
        if (kb + 1 < NKB) { load_stage((kb + 1) & 1, kb + 1); cp_commit(); }
        if (kb + 1 < NKB) cp_wait<1>(); else cp_wait<0>();
        __syncthreads();

        const uint32_t aT = sbase + (kb & 1) * GSTAGE_BYTES;
        const uint32_t wT = aT + GTILE_BYTES;

#pragma unroll
        for (int ks = 0; ks < GBK / 16; ks++) {
            const int kbyte = ks * 32;   // 16 bf16 = 32B
            uint32_t afr[4][4];
#pragma unroll
            for (int mt = 0; mt < 4; mt++) {
                int r = wm * 64 + mt * 16 + a_row;
                ldmx4(afr[mt], aT + r * GROW_BYTES + kbyte + a_kby);
            }
            uint32_t bfr[2][4];
#pragma unroll
            for (int np = 0; np < 2; np++) {
                int r = wn * 32 + np * 16 + b_row;
                ldmx4(bfr[np], wT + r * GROW_BYTES + kbyte + b_kby);
            }
#pragma unroll
            for (int mt = 0; mt < 4; mt++) {
#pragma unroll
                for (int nt = 0; nt < 4; nt++) {
                    const uint32_t* bp = &bfr[nt >> 1][(nt & 1) * 2];
                    mma16816(acc[mt][nt], afr[mt], bp);
                }
            }
        }
        __syncthreads();
    }

    // epilogue (canonical C map: c0,c1 at (row=grp, col=tig*2), c2,c3 at row+8)
#pragma unroll
    for (int mt = 0; mt < 4; mt++) {
        int r0 = m0 + wm * 64 + mt * 16 + grp;
#pragma unroll
        for (int nt = 0; nt < 4; nt++) {
            int cc = n0 + wn * 32 + nt * 8 + tig * 2;
            *(float2*)(C + (size_t)r0 * N + cc) =
                make_float2(acc[mt][nt][0], acc[mt][nt][1]);
            *(float2*)(C + (size_t)(r0 + 8) * N + cc) =
                make_float2(acc[mt][nt][2], acc[mt][nt][3]);
        }
    }
}

// ===========================================================================
// fp32 SGEMM (small GEMMs): C[M,N] = A[M,K(lda)] * W[N,K]^T
// EPI: 0 = plain, 1 = +bias then softplus
// ===========================================================================
template <int EPI>
__global__ __launch_bounds__(256)
void sgemm_kernel(const float* __restrict__ A, const float* __restrict__ W,
                  float* __restrict__ C, const float* __restrict__ bias,
                  int M, int N, int Kd, int lda)
{
    constexpr int BM = 128, BN = 128, BK = 8;
    __shared__ float As[BK][BM + 4];
    __shared__ float Bs[BK][BN + 4];

    const int tid = threadIdx.x;
    const int m0 = blockIdx.y * BM;
    const int n0 = blockIdx.x * BN;
    const int ty = tid >> 4;
    const int tx = tid & 15;

    const int lr = tid >> 1;
    const int lc = (tid & 1) * 4;
    const float* Aptr = A + (size_t)(m0 + lr) * lda + lc;
    const bool wvalid = (n0 + lr) < N;
    const float* Wptr = W + (size_t)(n0 + lr) * Kd + lc;

    float acc[8][8];
#pragma unroll
    for (int i = 0; i < 8; i++)
#pragma unroll
        for (int j = 0; j < 8; j++) acc[i][j] = 0.0f;

    for (int k0 = 0; k0 < Kd; k0 += BK) {
        float4 av = *(const float4*)(Aptr + k0);
        float4 wv = wvalid ? *(const float4*)(Wptr + k0) : make_float4(0.f, 0.f, 0.f, 0.f);

        __syncthreads();
        As[lc + 0][lr] = av.x;
        As[lc + 1][lr] = av.y;
        As[lc + 2][lr] = av.z;
        As[lc + 3][lr] = av.w;
        Bs[lc + 0][lr] = wv.x;
        Bs[lc + 1][lr] = wv.y;
        Bs[lc + 2][lr] = wv.z;
        Bs[lc + 3][lr] = wv.w;
        __syncthreads();

#pragma unroll
        for (int kk = 0; kk < BK; kk++) {
            float a[8], b[8];
            *(float4*)(a)     = *(const float4*)(&As[kk][ty * 8]);
            *(float4*)(a + 4) = *(const float4*)(&As[kk][ty * 8 + 4]);
            *(float4*)(b)     = *(const float4*)(&Bs[kk][tx * 8]);
            *(float4*)(b + 4) = *(const float4*)(&Bs[kk][tx * 8 + 4]);
#pragma unroll
            for (int i = 0; i < 8; i++)
#pragma unroll
                for (int j = 0; j < 8; j++)
                    acc[i][j] = fmaf(a[i], b[j], acc[i][j]);
        }
    }

#pragma unroll
    for (int i = 0; i < 8; i++) {
        int m = m0 + ty * 8 + i;
#pragma unroll
        for (int j = 0; j < 8; j++) {
            int n = n0 + tx * 8 + j;
            if (n < N) {
                float v = acc[i][j];
                if (EPI == 1) v = softplusf(v + bias[n]);
                C[(size_t)m * N + n] = v;
            }
        }
    }
}

// ===========================================================================
// depthwise causal conv (K=4) + bias + SiLU
// ===========================================================================
__global__ void conv_silu_kernel(const float* __restrict__ proj,
                                 const float* __restrict__ cw,
                                 const float* __restrict__ cb,
                                 float* __restrict__ xl)
{
    int idx = blockIdx.x * blockDim.x + threadIdx.x;
    if (idx >= BQ * LQ * IQ) return;
    int i  = idx % IQ;
    int bl = idx / IQ;
    int l  = bl % LQ;

    float w0 = cw[i * CK + 0], w1 = cw[i * CK + 1],
          w2 = cw[i * CK + 2], w3 = cw[i * CK + 3];
    const float* xp = proj + (size_t)bl * (2 * IQ) + i;
    const int str = 2 * IQ;

    float acc = cb[i];
    if (l >= 3) acc = fmaf(xp[-3 * str], w0, acc);
    if (l >= 2) acc = fmaf(xp[-2 * str], w1, acc);
    if (l >= 1) acc = fmaf(xp[-1 * str], w2, acc);
    acc = fmaf(xp[0], w3, acc);

    xl[idx] = siluf(acc);
}

// ===========================================================================
// selective scan: each warp owns 2 channels; lane = (sub<<4) | n
// ===========================================================================
__global__ __launch_bounds__(256)
void scan_kernel(const float* __restrict__ xl,
                 const float* __restrict__ dt,
                 const float* __restrict__ ssm,
                 const float* __restrict__ A_log,
                 float* __restrict__ y)
{
    int gtid = blockIdx.x * blockDim.x + threadIdx.x;
    int warp = gtid >> 5;
    int lane = threadIdx.x & 31;
    int sub  = lane >> 4;
    int n    = lane & 15;
    int ch   = warp * 2 + sub;
    if (ch >= BQ * IQ) return;
    int b = ch / IQ;
    int i = ch % IQ;

    const float Av = -expf(A_log[i * NQ + n]);

    const float* xp  = xl  + (size_t)b * LQ * IQ + i;
    const float* dtp = dt  + (size_t)b * LQ * IQ + i;
    const float* Bp  = ssm + (size_t)b * LQ * PQ + RQ + n;
    const float* Cp  = Bp + NQ;
    float*       yp  = y   + (size_t)b * LQ * IQ + i;

    float h = 0.0f;
    for (int l = 0; l < LQ; l++) {
        float xv  = xp [(size_t)l * IQ];
        float dtv = dtp[(size_t)l * IQ];
        float Bn  = Bp [(size_t)l * PQ];
        float Cn  = Cp [(size_t)l * PQ];

        float dA = expf(dtv * Av);
        h = fmaf(h, dA, dtv * Bn * xv);
        float c = h * Cn;
        c += __shfl_xor_sync(0xffffffffu, c, 8);
        c += __shfl_xor_sync(0xffffffffu, c, 4);
        c += __shfl_xor_sync(0xffffffffu, c, 2);
        c += __shfl_xor_sync(0xffffffffu, c, 1);
        if (n == 0) yp[(size_t)l * IQ] = c;
    }
}

// ===========================================================================
// gating fused with triple bf16 split:
//   v = (y_scan + xl*D) * silu(gate);  y3 = [vh | vh | vl]
// ===========================================================================
__global__ void gate_split3_kernel(const float* __restrict__ proj,
                                   const float* __restrict__ xl,
                                   const float* __restrict__ Dw,
                                   const float* __restrict__ yscan,
                                   __nv_bfloat16* __restrict__ y3)
{
    int idx = blockIdx.x * blockDim.x + threadIdx.x;
    if (idx >= BQ * LQ * IQ) return;
    int i  = idx % IQ;
    int bl = idx / IQ;
    float g = proj[(size_t)bl * (2 * IQ) + IQ + i];
    float v = (yscan[idx] + xl[idx] * Dw[i]) * siluf(g);
    __nv_bfloat16 h = __float2bfloat16(v);
    __nv_bfloat16 l = __float2bfloat16(v - __bfloat162float(h));
    size_t base = (size_t)bl * 3 * IQ;
    y3[base + i] = h;
    y3[base + IQ + i] = h;
    y3[base + 2 * IQ + i] = l;
}

// ===========================================================================
extern "C" void kernel_launch(void* const* d_in, const int* in_sizes, int n_in,
                              void* d_out, int out_size)
{
    const float* hidden    = (const float*)d_in[0];  // [B,L,H]
    const float* in_proj_w = (const float*)d_in[1];  // [2I,H]
    const float* conv_w    = (const float*)d_in[2];  // [I,K]
    const float* conv_b    = (const float*)d_in[3];  // [I]
    const float* x_proj_w  = (const float*)d_in[4];  // [96,I]
    const float* dt_proj_w = (const float*)d_in[5];  // [I,R]
    const float* dt_proj_b = (const float*)d_in[6];  // [I]
    const float* A_log     = (const float*)d_in[7];  // [I,N]
    const float* Dw        = (const float*)d_in[8];  // [I]
    const float* out_proj_w= (const float*)d_in[9];  // [H,I]  (K = IQ!)
    float* out = (float*)d_out;                      // [B,L,H]

    float *proj, *xl, *ssm, *dt, *y;
    char* arena;
    cudaGetSymbolAddress((void**)&proj,  g_proj);
    cudaGetSymbolAddress((void**)&xl,    g_xl);
    cudaGetSymbolAddress((void**)&ssm,   g_ssm);
    cudaGetSymbolAddress((void**)&dt,    g_dt);
    cudaGetSymbolAddress((void**)&y,     g_y);
    cudaGetSymbolAddress((void**)&arena, g_arena);

    __nv_bfloat16* wout3 = (__nv_bfloat16*)(arena + OFF_WOUT3);
    __nv_bfloat16* hs3   = (__nv_bfloat16*)(arena + OFF_HS3);
    __nv_bfloat16* win3  = (__nv_bfloat16*)(arena + OFF_WIN3);
    __nv_bfloat16* y3    = (__nv_bfloat16*)(arena + OFF_Y3);   // overlays hs3/win3

    cudaFuncSetAttribute(tc_gemm_kernel,
                         cudaFuncAttributeMaxDynamicSharedMemorySize, GSMEM_BYTES);

    const int M = BQ * LQ;  // 8192

    // 0) bf16 triple splits (out_proj_w is [H, I] -> K = IQ)
    {
        int n3 = HQ * IQ;
        split3_W_kernel<<<(n3 + 255) / 256, 256>>>(out_proj_w, wout3, HQ, IQ);
        int n1 = M * HQ;
        split3_A_kernel<<<(n1 + 255) / 256, 256>>>(hidden, hs3, M, HQ);
        int n2 = 2 * IQ * HQ;
        split3_W_kernel<<<(n2 + 255) / 256, 256>>>(in_proj_w, win3, 2 * IQ, HQ);
    }
    // 1) in_proj on tensor cores: proj[M, 2I] = hidden @ in_proj_w^T  (K'=3072)
    {
        dim3 grid((2 * IQ) / GBN, M / GBM);
        tc_gemm_kernel<<<grid, 256, GSMEM_BYTES>>>(hs3, win3, proj, M, 2 * IQ, 3 * HQ);
    }
    // 2) depthwise conv + silu -> xl[M, I]
    {
        int total = BQ * LQ * IQ;
        conv_silu_kernel<<<(total + 255) / 256, 256>>>(proj, conv_w, conv_b, xl);
    }
    // 3) x_proj: ssm[M, 96] = xl @ x_proj_w^T   (fp32)
    {
        dim3 grid(1, M / 128);
        sgemm_kernel<0><<<grid, 256>>>(xl, x_proj_w, ssm, nullptr, M, PQ, IQ, IQ);
    }
    // 4) dt_proj + softplus (fp32)
    {
        dim3 grid(IQ / 128, M / 128);
        sgemm_kernel<1><<<grid, 256>>>(ssm, dt_proj_w, dt, dt_proj_b, M, IQ, RQ, PQ);
    }
    // 5) selective scan -> y[M, I]
    {
        int nthreads = (BQ * IQ / 2) * 32;
        scan_kernel<<<nthreads / 256, 256>>>(xl, dt, ssm, A_log, y);
    }
    // 6) gating + triple split -> y3 [M, 3*I=6144]
    {
        int total = BQ * LQ * IQ;
        gate_split3_kernel<<<(total + 255) / 256, 256>>>(proj, xl, Dw, y, y3);
    }
    // 7) out_proj on tensor cores: out[M, H] = y @ out_proj_w^T  (K'=3*I=6144)
    {
        dim3 grid(HQ / GBN, M / GBM);
        tc_gemm_kernel<<<grid, 256, GSMEM_BYTES>>>(y3, wout3, out, M, HQ, 3 * IQ);
    }
}